// round 5
// baseline (speedup 1.0000x reference)
#include <cuda_runtime.h>

#define NB   16384
#define DIN  1024
#define NL   4
#define NK   1024
#define CB   512

// Scratch (no cudaMalloc allowed)
__device__ float g_resid[NB * CB];      // 33.5 MB residual
__device__ int   g_ids[NB * NL];
__device__ float g_cnorm[NL * NK];

// ---------------------------------------------------------------------------
// ||c||^2 per code, one warp per code
// ---------------------------------------------------------------------------
__global__ void cnorm_kernel(const float* __restrict__ codebooks) {
    int warp = (blockIdx.x * blockDim.x + threadIdx.x) >> 5;
    int lane = threadIdx.x & 31;
    if (warp >= NL * NK) return;
    const float* c = codebooks + (size_t)warp * CB;
    float s = 0.f;
    for (int t = lane; t < CB; t += 32) { float v = c[t]; s += v * v; }
    #pragma unroll
    for (int o = 16; o > 0; o >>= 1) s += __shfl_xor_sync(0xffffffffu, s, o);
    if (lane == 0) g_cnorm[warp] = s;
}

// ---------------------------------------------------------------------------
// Encoder GEMM: R = X[NB,DIN] @ W[DIN,CB] + b   (tile 128x128x8, thread 8x8)
// ---------------------------------------------------------------------------
__global__ __launch_bounds__(256) void enc_gemm(const float* __restrict__ X,
                                                const float* __restrict__ W,
                                                const float* __restrict__ bias) {
    __shared__ float As[8][136];   // [kk][m]
    __shared__ float Bs[8][136];   // [kk][n]
    const int tid = threadIdx.x;
    const int tx = tid & 15, ty = tid >> 4;
    const int m0 = blockIdx.y * 128, n0 = blockIdx.x * 128;

    const int am  = tid >> 1;           // 0..127
    const int akv = (tid & 1) * 4;      // 0 or 4
    const int bk  = tid >> 5;           // 0..7
    const int bn  = (tid & 31) * 4;     // 0..124

    float acc[8][8] = {};

    for (int k0 = 0; k0 < DIN; k0 += 8) {
        float4 av = *(const float4*)&X[(size_t)(m0 + am) * DIN + k0 + akv];
        float4 bv = *(const float4*)&W[(size_t)(k0 + bk) * CB + n0 + bn];
        __syncthreads();
        As[akv + 0][am] = av.x; As[akv + 1][am] = av.y;
        As[akv + 2][am] = av.z; As[akv + 3][am] = av.w;
        *(float4*)&Bs[bk][bn] = bv;
        __syncthreads();
        #pragma unroll
        for (int kk = 0; kk < 8; kk++) {
            float4 a0 = *(const float4*)&As[kk][ty * 8];
            float4 a1 = *(const float4*)&As[kk][ty * 8 + 4];
            float4 b0 = *(const float4*)&Bs[kk][tx * 8];
            float4 b1 = *(const float4*)&Bs[kk][tx * 8 + 4];
            float a[8] = {a0.x, a0.y, a0.z, a0.w, a1.x, a1.y, a1.z, a1.w};
            float b[8] = {b0.x, b0.y, b0.z, b0.w, b1.x, b1.y, b1.z, b1.w};
            #pragma unroll
            for (int i = 0; i < 8; i++)
                #pragma unroll
                for (int j = 0; j < 8; j++)
                    acc[i][j] += a[i] * b[j];
        }
    }
    #pragma unroll
    for (int i = 0; i < 8; i++) {
        int m = m0 + ty * 8 + i;
        #pragma unroll
        for (int j = 0; j < 8; j++) {
            int n = n0 + tx * 8 + j;
            g_resid[(size_t)m * CB + n] = acc[i][j] + bias[n];
        }
    }
}

// ---------------------------------------------------------------------------
// One VQ layer: for 128 rows, score all 1024 codes (d = ||c||^2 - 2 r.c),
// running argmin, then residual -= codebook[argmin].
// ---------------------------------------------------------------------------
__global__ __launch_bounds__(256) void layer_kernel(const float* __restrict__ codebooks,
                                                    int layer) {
    __shared__ float As[8][136];
    __shared__ float Bs[8][136];
    __shared__ float red_d[128][17];
    __shared__ int   red_i[128][17];
    __shared__ int   bestidx[128];

    const float* Cb = codebooks + (size_t)layer * NK * CB;
    const float* cn = g_cnorm + layer * NK;

    const int tid = threadIdx.x;
    const int tx = tid & 15, ty = tid >> 4;
    const int m0 = blockIdx.x * 128;

    const int am  = tid >> 1;
    const int akv = (tid & 1) * 4;
    const int bn  = tid >> 1;           // code within tile, 0..127
    const int bkv = (tid & 1) * 4;

    float best_d[8];
    int   best_i[8];
    #pragma unroll
    for (int i = 0; i < 8; i++) { best_d[i] = 3.4e38f; best_i[i] = 0; }

    for (int t = 0; t < NK; t += 128) {
        float acc[8][8] = {};
        for (int k0 = 0; k0 < CB; k0 += 8) {
            float4 av = *(const float4*)&g_resid[(size_t)(m0 + am) * CB + k0 + akv];
            float4 bv = *(const float4*)&Cb[(size_t)(t + bn) * CB + k0 + bkv];
            __syncthreads();
            As[akv + 0][am] = av.x; As[akv + 1][am] = av.y;
            As[akv + 2][am] = av.z; As[akv + 3][am] = av.w;
            Bs[bkv + 0][bn] = bv.x; Bs[bkv + 1][bn] = bv.y;
            Bs[bkv + 2][bn] = bv.z; Bs[bkv + 3][bn] = bv.w;
            __syncthreads();
            #pragma unroll
            for (int kk = 0; kk < 8; kk++) {
                float4 a0 = *(const float4*)&As[kk][ty * 8];
                float4 a1 = *(const float4*)&As[kk][ty * 8 + 4];
                float4 b0 = *(const float4*)&Bs[kk][tx * 8];
                float4 b1 = *(const float4*)&Bs[kk][tx * 8 + 4];
                float a[8] = {a0.x, a0.y, a0.z, a0.w, a1.x, a1.y, a1.z, a1.w};
                float b[8] = {b0.x, b0.y, b0.z, b0.w, b1.x, b1.y, b1.z, b1.w};
                #pragma unroll
                for (int i = 0; i < 8; i++)
                    #pragma unroll
                    for (int j = 0; j < 8; j++)
                        acc[i][j] += a[i] * b[j];
            }
        }
        // fold this code tile into running argmin (codes visited in increasing order)
        #pragma unroll
        for (int j = 0; j < 8; j++) {
            int code = t + tx * 8 + j;
            float c2 = cn[code];
            #pragma unroll
            for (int i = 0; i < 8; i++) {
                float d = c2 - 2.f * acc[i][j];
                if (d < best_d[i]) { best_d[i] = d; best_i[i] = code; }
            }
        }
    }

    __syncthreads();
    #pragma unroll
    for (int i = 0; i < 8; i++) {
        red_d[ty * 8 + i][tx] = best_d[i];
        red_i[ty * 8 + i][tx] = best_i[i];
    }
    __syncthreads();
    if (tid < 128) {
        float bd = red_d[tid][0];
        int   bi = red_i[tid][0];
        #pragma unroll
        for (int x = 1; x < 16; x++) {
            float d = red_d[tid][x];
            int   ii = red_i[tid][x];
            // tx increasing => code increasing; strict < keeps first (lowest) index
            if (d < bd || (d == bd && ii < bi)) { bd = d; bi = ii; }
        }
        bestidx[tid] = bi;
        g_ids[(size_t)(m0 + tid) * NL + layer] = bi;
    }
    __syncthreads();

    // residual -= codebook[best]
    const int nvec = 128 * (CB / 4);
    for (int e = tid; e < nvec; e += 256) {
        int row  = e / (CB / 4);
        int col4 = (e % (CB / 4)) * 4;
        int ci   = bestidx[row];
        float4 r = *(const float4*)&g_resid[(size_t)(m0 + row) * CB + col4];
        float4 c = *(const float4*)&Cb[(size_t)ci * CB + col4];
        r.x -= c.x; r.y -= c.y; r.z -= c.z; r.w -= c.w;
        *(float4*)&g_resid[(size_t)(m0 + row) * CB + col4] = r;
    }
}

// ---------------------------------------------------------------------------
// Decoder: recon[b,j] = sum_l ids[b,l]*dec_W[l,j] + dec_b[j]
// ---------------------------------------------------------------------------
__global__ void decode_kernel(const float* __restrict__ dec_W,
                              const float* __restrict__ dec_b,
                              float* __restrict__ out) {
    int idx = blockIdx.x * blockDim.x + threadIdx.x;
    if (idx >= NB * CB) return;
    int b = idx / CB, j = idx % CB;
    const int* ids = &g_ids[b * NL];
    float s = dec_b[j];
    #pragma unroll
    for (int l = 0; l < NL; l++)
        s += (float)ids[l] * dec_W[l * CB + j];
    out[idx] = s;
}

__global__ void ids_out_kernel(float* __restrict__ out, int n) {
    int idx = blockIdx.x * blockDim.x + threadIdx.x;
    if (idx < n) out[idx] = (float)g_ids[idx];
}

// ---------------------------------------------------------------------------
extern "C" void kernel_launch(void* const* d_in, const int* in_sizes, int n_in,
                              void* d_out, int out_size) {
    (void)in_sizes; (void)n_in;
    const float* X    = (const float*)d_in[0];
    const float* encW = (const float*)d_in[1];
    const float* encb = (const float*)d_in[2];
    const float* cbs  = (const float*)d_in[3];
    const float* decW = (const float*)d_in[4];
    const float* decb = (const float*)d_in[5];
    float* out = (float*)d_out;

    cnorm_kernel<<<(NL * NK * 32 + 255) / 256, 256>>>(cbs);

    dim3 gEnc(CB / 128, NB / 128);
    enc_gemm<<<gEnc, 256>>>(X, encW, encb);

    for (int l = 0; l < NL; l++)
        layer_kernel<<<NB / 128, 256>>>(cbs, l);

    const long long RE = (long long)NB * CB;   // 8388608
    const long long ID = (long long)NB * NL;   // 65536

    if ((long long)out_size >= RE) {
        decode_kernel<<<(NB * CB + 255) / 256, 256>>>(decW, decb, out);
        if ((long long)out_size >= RE + ID)
            ids_out_kernel<<<(int)((ID + 255) / 256), 256>>>(out + RE, (int)ID);
    } else {
        // fallback: only ids requested
        ids_out_kernel<<<(out_size + 255) / 256, 256>>>(out, out_size);
    }
}

// round 9
// speedup vs baseline: 2.2497x; 2.2497x over previous
#include <cuda_runtime.h>
#include <cuda_bf16.h>
#include <cstdint>

#define NB   16384
#define DIN  1024
#define NL   4
#define NK   1024
#define CB   512

// ---------------------------------------------------------------------------
// Device scratch (no cudaMalloc allowed); 16B aligned for cp.async/float4.
// ---------------------------------------------------------------------------
__device__ __align__(16) float g_residf[NB * CB];   // fp32 residual (exact chain)
__device__ __align__(16) int   g_ids[NB * NL];
__device__ __align__(16) float g_cnorm[NL * NK];
__device__ __align__(16) __nv_bfloat16 g_Ahi[NB * CB];        // bf16 hi of residual
__device__ __align__(16) __nv_bfloat16 g_Chi[NL * NK * CB];   // bf16 hi of codebooks
// encoder operands: 2-way bf16 splits (3 pair-terms: 00, 01, 10)
__device__ __align__(16) __nv_bfloat16 g_X0[NB * DIN];
__device__ __align__(16) __nv_bfloat16 g_X1[NB * DIN];
__device__ __align__(16) __nv_bfloat16 g_W0[CB * DIN];        // enc_W^T splits [n][k]
__device__ __align__(16) __nv_bfloat16 g_W1[CB * DIN];

// ---------------------------------------------------------------------------
// helpers
// ---------------------------------------------------------------------------
__device__ __forceinline__ uint32_t smem_u32(const void* p) {
    uint32_t a;
    asm("{ .reg .u64 t; cvta.to.shared.u64 t, %1; cvt.u32.u64 %0, t; }"
        : "=r"(a) : "l"(p));
    return a;
}
__device__ __forceinline__ void cpa16(uint32_t s, const void* g) {
    asm volatile("cp.async.cg.shared.global [%0], [%1], 16;" :: "r"(s), "l"(g));
}
__device__ __forceinline__ uint32_t swz(uint32_t b) { return b ^ ((b >> 3) & 0x70); }

__device__ __forceinline__ void ldmA(uint32_t* a, uint32_t addr) {
    asm volatile("ldmatrix.sync.aligned.m8n8.x4.shared.b16 {%0,%1,%2,%3}, [%4];"
                 : "=r"(a[0]), "=r"(a[1]), "=r"(a[2]), "=r"(a[3]) : "r"(addr));
}
__device__ __forceinline__ void ldmB(uint32_t* b, uint32_t addr) {
    asm volatile("ldmatrix.sync.aligned.m8n8.x2.shared.b16 {%0,%1}, [%2];"
                 : "=r"(b[0]), "=r"(b[1]) : "r"(addr));
}
__device__ __forceinline__ void mma16816(float* c, const uint32_t* a, const uint32_t* b) {
    asm volatile(
        "mma.sync.aligned.m16n8k16.row.col.f32.bf16.bf16.f32 "
        "{%0,%1,%2,%3}, {%4,%5,%6,%7}, {%8,%9}, {%0,%1,%2,%3};"
        : "+f"(c[0]), "+f"(c[1]), "+f"(c[2]), "+f"(c[3])
        : "r"(a[0]), "r"(a[1]), "r"(a[2]), "r"(a[3]), "r"(b[0]), "r"(b[1]));
}

// ---------------------------------------------------------------------------
// Prep kernels
// ---------------------------------------------------------------------------
__global__ void cnorm_kernel(const float* __restrict__ codebooks) {
    int warp = (blockIdx.x * blockDim.x + threadIdx.x) >> 5;
    int lane = threadIdx.x & 31;
    if (warp >= NL * NK) return;
    const float* c = codebooks + (size_t)warp * CB;
    float s = 0.f;
    for (int t = lane; t < CB; t += 32) { float v = c[t]; s += v * v; }
    #pragma unroll
    for (int o = 16; o > 0; o >>= 1) s += __shfl_xor_sync(0xffffffffu, s, o);
    if (lane == 0) g_cnorm[warp] = s;
}

__global__ void xsplit_kernel(const float* __restrict__ X) {
    int i = blockIdx.x * blockDim.x + threadIdx.x;
    if (i >= NB * DIN) return;
    float v = X[i];
    __nv_bfloat16 s0 = __float2bfloat16(v);
    __nv_bfloat16 s1 = __float2bfloat16(v - __bfloat162float(s0));
    g_X0[i] = s0; g_X1[i] = s1;
}

__global__ void cbhi_kernel(const float* __restrict__ Cbs) {
    int i = blockIdx.x * blockDim.x + threadIdx.x;
    if (i >= NL * NK * CB) return;
    g_Chi[i] = __float2bfloat16(Cbs[i]);
}

__global__ void wsplitT_kernel(const float* __restrict__ W) {  // [DIN][CB] -> [CB][DIN]
    int i = blockIdx.x * blockDim.x + threadIdx.x;
    if (i >= CB * DIN) return;
    int n = i / DIN, k = i % DIN;
    float v = W[(size_t)k * CB + n];
    __nv_bfloat16 s0 = __float2bfloat16(v);
    __nv_bfloat16 s1 = __float2bfloat16(v - __bfloat162float(s0));
    g_W0[i] = s0; g_W1[i] = s1;
}

// ---------------------------------------------------------------------------
// Encoder: r0 = X @ W + b via 3-pair bf16 split on mma.sync (err ~1e-4 abs)
// CTA tile 128x128, 8 warps (2m x 4n), warp tile 64x32. 48 K-chunks of 64.
// ---------------------------------------------------------------------------
__global__ __launch_bounds__(256) void enc_mma_kernel(const float* __restrict__ encb) {
    extern __shared__ char dsm[];
    const uint32_t sb = smem_u32(dsm);
    const uint32_t Abuf[2] = { sb,          sb + 16384 };
    const uint32_t Bbuf[2] = { sb + 32768,  sb + 49152 };

    const int tid = threadIdx.x, wid = tid >> 5, lane = tid & 31;
    const int wm = wid >> 2, wn = wid & 3;
    const int g = lane >> 2, q = lane & 3;
    const int m0 = blockIdx.y * 128, n0 = blockIdx.x * 128;

    const __nv_bfloat16* TA[3] = { g_X0, g_X0, g_X1 };
    const __nv_bfloat16* TB[3] = { g_W0, g_W1, g_W0 };

    float acc[4][4][4];
    #pragma unroll
    for (int i = 0; i < 4; i++)
        #pragma unroll
        for (int j = 0; j < 4; j++)
            #pragma unroll
            for (int k = 0; k < 4; k++) acc[i][j][k] = 0.f;

    auto issue = [&](int p, int b) {
        int term = p >> 4, k0 = (p & 15) * 64;
        const __nv_bfloat16* As = TA[term];
        const __nv_bfloat16* Bs = TB[term];
        #pragma unroll
        for (int it = 0; it < 4; it++) {
            int w = tid + it * 256;
            int row = w >> 3, sg = w & 7;
            cpa16(Abuf[b] + swz((uint32_t)(row * 128 + sg * 16)),
                  As + (size_t)(m0 + row) * DIN + k0 + sg * 8);
        }
        #pragma unroll
        for (int it = 0; it < 4; it++) {
            int w = tid + it * 256;
            int row = w >> 3, sg = w & 7;
            cpa16(Bbuf[b] + swz((uint32_t)(row * 128 + sg * 16)),
                  Bs + (size_t)(n0 + row) * DIN + k0 + sg * 8);
        }
        asm volatile("cp.async.commit_group;");
    };

    issue(0, 0);

    #pragma unroll 1
    for (int p = 0; p < 48; p++) {
        if (p + 1 < 48) {
            issue(p + 1, (p + 1) & 1);
            asm volatile("cp.async.wait_group 1;" ::: "memory");
        } else {
            asm volatile("cp.async.wait_group 0;" ::: "memory");
        }
        __syncthreads();

        const uint32_t ab = Abuf[p & 1], bb = Bbuf[p & 1];
        #pragma unroll
        for (int kf = 0; kf < 4; kf++) {
            uint32_t af[4][4], bf[4][2];
            #pragma unroll
            for (int mf = 0; mf < 4; mf++) {
                int arow = wm * 64 + mf * 16 + (lane & 7) + ((lane >> 3) & 1) * 8;
                uint32_t koff = kf * 32 + (lane >> 4) * 16;
                ldmA(af[mf], ab + swz((uint32_t)(arow * 128) + koff));
            }
            #pragma unroll
            for (int nf = 0; nf < 4; nf++) {
                int l = lane & 15;
                int nrow = wn * 32 + nf * 8 + (l & 7);
                uint32_t koff = kf * 32 + ((l >> 3) & 1) * 16;
                ldmB(bf[nf], bb + swz((uint32_t)(nrow * 128) + koff));
            }
            #pragma unroll
            for (int mf = 0; mf < 4; mf++)
                #pragma unroll
                for (int nf = 0; nf < 4; nf++)
                    mma16816(acc[mf][nf], af[mf], bf[nf]);
        }
        __syncthreads();
    }

    // epilogue: bias + write fp32 residual and bf16 hi
    #pragma unroll
    for (int mf = 0; mf < 4; mf++) {
        #pragma unroll
        for (int nf = 0; nf < 4; nf++) {
            #pragma unroll
            for (int j = 0; j < 4; j++) {
                int row = m0 + wm * 64 + mf * 16 + g + (j >> 1) * 8;
                int col = n0 + wn * 32 + nf * 8 + q * 2 + (j & 1);
                float v = acc[mf][nf][j] + __ldg(&encb[col]);
                size_t o = (size_t)row * CB + col;
                g_residf[o] = v;
                g_Ahi[o]    = __float2bfloat16(v);
            }
        }
    }
}

// ---------------------------------------------------------------------------
// VQ layer: coarse bf16 scores (mma.sync) + top-3/owner + exact fp32 rescore
// within margin, then residual update + re-split hi.
// CTA: 128 rows x all 1024 codes. A (128x512 bf16) persistent in smem.
// ---------------------------------------------------------------------------
__global__ __launch_bounds__(256) void vq_layer_kernel(const float* __restrict__ cbs,
                                                       int layer) {
    extern __shared__ char dsm[];
    const uint32_t sb    = smem_u32(dsm);
    const uint32_t A_off = sb;                 // 8 tiles x 16KB = 128KB
    const uint32_t B_off = sb + 131072;        // 2 bufs x 16KB
    float* red_d = (float*)dsm;                // [128][48] aliases A (used after loop)
    int*   red_i = (int*)(dsm + 128 * 48 * 4);
    __shared__ int bsel[128];

    const int tid = threadIdx.x, wid = tid >> 5, lane = tid & 31;
    const int wm = wid >> 2, wn = wid & 3;
    const int g = lane >> 2, q = lane & 3;
    const int m0 = blockIdx.x * 128;

    const __nv_bfloat16* Chi = g_Chi + (size_t)layer * NK * CB;
    const float* cn  = g_cnorm + layer * NK;
    const float* CbL = cbs + (size_t)layer * NK * CB;

    // load A (residual hi), 8 K-tiles of [128][64]
    #pragma unroll 1
    for (int it = 0; it < 32; it++) {
        int s = tid + it * 256;              // 0..8191 sectors
        int tile = s >> 10, w = s & 1023;
        int row = w >> 3, sg = w & 7;
        cpa16(A_off + tile * 16384 + swz((uint32_t)(row * 128 + sg * 16)),
              g_Ahi + (size_t)(m0 + row) * CB + tile * 64 + sg * 8);
    }
    asm volatile("cp.async.commit_group;");

    // prefetch B chunk 0 (nt=0, kc=0)
    #pragma unroll
    for (int it = 0; it < 4; it++) {
        int w = tid + it * 256;
        int row = w >> 3, sg = w & 7;
        cpa16(B_off + swz((uint32_t)(row * 128 + sg * 16)),
              Chi + (size_t)row * CB + sg * 8);
    }
    asm volatile("cp.async.commit_group;");

    float t3d[8][3]; int t3i[8][3];
    #pragma unroll
    for (int r = 0; r < 8; r++) {
        t3d[r][0] = t3d[r][1] = t3d[r][2] = 3.4e38f;
        t3i[r][0] = t3i[r][1] = t3i[r][2] = 0;
    }

    float acc[4][4][4];

    #pragma unroll 1
    for (int p = 0; p < 64; p++) {
        const int nt = p >> 3, kc = p & 7;
        if (p + 1 < 64) {
            const int nnt = (p + 1) >> 3, nkc = (p + 1) & 7;
            uint32_t bb = B_off + ((p + 1) & 1) * 16384;
            #pragma unroll
            for (int it = 0; it < 4; it++) {
                int w = tid + it * 256;
                int row = w >> 3, sg = w & 7;
                cpa16(bb + swz((uint32_t)(row * 128 + sg * 16)),
                      Chi + (size_t)(nnt * 128 + row) * CB + nkc * 64 + sg * 8);
            }
            asm volatile("cp.async.commit_group;");
            asm volatile("cp.async.wait_group 1;" ::: "memory");
        } else {
            asm volatile("cp.async.wait_group 0;" ::: "memory");
        }
        __syncthreads();

        if (kc == 0) {
            #pragma unroll
            for (int i = 0; i < 4; i++)
                #pragma unroll
                for (int j = 0; j < 4; j++)
                    #pragma unroll
                    for (int k = 0; k < 4; k++) acc[i][j][k] = 0.f;
        }

        const uint32_t ab = A_off + kc * 16384;
        const uint32_t bb = B_off + (p & 1) * 16384;
        #pragma unroll
        for (int kf = 0; kf < 4; kf++) {
            uint32_t af[4][4], bf[4][2];
            #pragma unroll
            for (int mf = 0; mf < 4; mf++) {
                int arow = wm * 64 + mf * 16 + (lane & 7) + ((lane >> 3) & 1) * 8;
                uint32_t koff = kf * 32 + (lane >> 4) * 16;
                ldmA(af[mf], ab + swz((uint32_t)(arow * 128) + koff));
            }
            #pragma unroll
            for (int nf = 0; nf < 4; nf++) {
                int l = lane & 15;
                int nrow = wn * 32 + nf * 8 + (l & 7);
                uint32_t koff = kf * 32 + ((l >> 3) & 1) * 16;
                ldmB(bf[nf], bb + swz((uint32_t)(nrow * 128) + koff));
            }
            #pragma unroll
            for (int mf = 0; mf < 4; mf++)
                #pragma unroll
                for (int nf = 0; nf < 4; nf++)
                    mma16816(acc[mf][nf], af[mf], bf[nf]);
        }

        if (kc == 7) {   // fold this code tile into per-thread top-3
            #pragma unroll
            for (int mf = 0; mf < 4; mf++) {
                #pragma unroll
                for (int nf = 0; nf < 4; nf++) {
                    int colbase = nt * 128 + wn * 32 + nf * 8 + q * 2;
                    #pragma unroll
                    for (int j = 0; j < 4; j++) {
                        int code = colbase + (j & 1);
                        float d = __ldg(&cn[code]) - 2.f * acc[mf][nf][j];
                        int rs = mf * 2 + (j >> 1);
                        if (d < t3d[rs][2]) {
                            if (d < t3d[rs][1]) {
                                t3d[rs][2] = t3d[rs][1]; t3i[rs][2] = t3i[rs][1];
                                if (d < t3d[rs][0]) {
                                    t3d[rs][1] = t3d[rs][0]; t3i[rs][1] = t3i[rs][0];
                                    t3d[rs][0] = d; t3i[rs][0] = code;
                                } else { t3d[rs][1] = d; t3i[rs][1] = code; }
                            } else { t3d[rs][2] = d; t3i[rs][2] = code; }
                        }
                    }
                }
            }
        }
        __syncthreads();
    }

    // dump per-owner top-3 (A smem region is free now)
    #pragma unroll
    for (int rs = 0; rs < 8; rs++) {
        int mf = rs >> 1, h = rs & 1;
        int row = wm * 64 + mf * 16 + g + h * 8;
        int owner = wn * 4 + q;
        #pragma unroll
        for (int j = 0; j < 3; j++) {
            red_d[row * 48 + owner * 3 + j] = t3d[rs][j];
            red_i[row * 48 + owner * 3 + j] = t3i[rs][j];
        }
    }
    __syncthreads();

    // exact fp32 rescore within margin of coarse min
    if (tid < 128) {
        int row = tid;
        float dmin = 3.4e38f;
        #pragma unroll 1
        for (int e = 0; e < 48; e++) dmin = fminf(dmin, red_d[row * 48 + e]);
        const float TAU = 1.5f;
        float bd = 3.4e38f; int bi = 0x7fffffff;
        const float* R = g_residf + (size_t)(m0 + row) * CB;
        #pragma unroll 1
        for (int e = 0; e < 48; e++) {
            if (red_d[row * 48 + e] <= dmin + TAU) {
                int c = red_i[row * 48 + e];
                const float* C = CbL + (size_t)c * CB;
                float s0 = 0.f, s1 = 0.f, s2 = 0.f, s3 = 0.f;
                #pragma unroll 4
                for (int k = 0; k < CB; k += 4) {
                    s0 += R[k]     * C[k];
                    s1 += R[k + 1] * C[k + 1];
                    s2 += R[k + 2] * C[k + 2];
                    s3 += R[k + 3] * C[k + 3];
                }
                float de = __ldg(&cn[c]) - 2.f * ((s0 + s1) + (s2 + s3));
                if (de < bd || (de == bd && c < bi)) { bd = de; bi = c; }
            }
        }
        bsel[row] = bi;
        g_ids[(size_t)(m0 + row) * NL + layer] = bi;
    }
    __syncthreads();

    // residual -= codebook[best]; store fp32 + bf16 hi for next layer
    #pragma unroll 1
    for (int e = tid; e < 128 * (CB / 4); e += 256) {
        int r = e >> 7, c4 = (e & 127) * 4;
        int ci = bsel[r];
        size_t ro = (size_t)(m0 + r) * CB + c4;
        float4 rv = *(float4*)&g_residf[ro];
        float4 cv = *(const float4*)&CbL[(size_t)ci * CB + c4];
        rv.x -= cv.x; rv.y -= cv.y; rv.z -= cv.z; rv.w -= cv.w;
        *(float4*)&g_residf[ro] = rv;
        if (layer < NL - 1) {
            __nv_bfloat162 h0{__float2bfloat16(rv.x), __float2bfloat16(rv.y)};
            __nv_bfloat162 h1{__float2bfloat16(rv.z), __float2bfloat16(rv.w)};
            *(__nv_bfloat162*)&g_Ahi[ro]     = h0;
            *(__nv_bfloat162*)&g_Ahi[ro + 2] = h1;
        }
    }
}

// ---------------------------------------------------------------------------
// Decoder + ids output (exact, unchanged from passing baseline)
// ---------------------------------------------------------------------------
__global__ void decode_kernel(const float* __restrict__ dec_W,
                              const float* __restrict__ dec_b,
                              float* __restrict__ out) {
    int idx = blockIdx.x * blockDim.x + threadIdx.x;
    if (idx >= NB * CB) return;
    int b = idx / CB, j = idx % CB;
    const int* ids = &g_ids[b * NL];
    float s = dec_b[j];
    #pragma unroll
    for (int l = 0; l < NL; l++)
        s += (float)ids[l] * dec_W[l * CB + j];
    out[idx] = s;
}

__global__ void ids_out_kernel(float* __restrict__ out, int n) {
    int idx = blockIdx.x * blockDim.x + threadIdx.x;
    if (idx < n) out[idx] = (float)g_ids[idx];
}

// ---------------------------------------------------------------------------
extern "C" void kernel_launch(void* const* d_in, const int* in_sizes, int n_in,
                              void* d_out, int out_size) {
    (void)in_sizes; (void)n_in;
    const float* X    = (const float*)d_in[0];
    const float* encW = (const float*)d_in[1];
    const float* encb = (const float*)d_in[2];
    const float* cbs  = (const float*)d_in[3];
    const float* decW = (const float*)d_in[4];
    const float* decb = (const float*)d_in[5];
    float* out = (float*)d_out;

    const int VQ_SMEM  = 131072 + 2 * 16384;   // 163840
    const int ENC_SMEM = 4 * 16384;            // 65536
    cudaFuncSetAttribute(vq_layer_kernel, cudaFuncAttributeMaxDynamicSharedMemorySize, VQ_SMEM);
    cudaFuncSetAttribute(enc_mma_kernel,  cudaFuncAttributeMaxDynamicSharedMemorySize, ENC_SMEM);

    // prep
    cnorm_kernel<<<(NL * NK * 32 + 255) / 256, 256>>>(cbs);
    xsplit_kernel<<<(NB * DIN + 255) / 256, 256>>>(X);
    cbhi_kernel<<<(NL * NK * CB + 255) / 256, 256>>>(cbs);
    wsplitT_kernel<<<(CB * DIN + 255) / 256, 256>>>(encW);

    // encoder (tensor cores, 3-pair split)
    dim3 gEnc(CB / 128, NB / 128);
    enc_mma_kernel<<<gEnc, 256, ENC_SMEM>>>(encb);

    // VQ layers (tensor-core coarse + exact rescore)
    for (int l = 0; l < NL; l++)
        vq_layer_kernel<<<NB / 128, 256, VQ_SMEM>>>(cbs, l);

    const long long RE = (long long)NB * CB;   // 8388608
    const long long ID = (long long)NB * NL;   // 65536

    if ((long long)out_size >= RE) {
        decode_kernel<<<(NB * CB + 255) / 256, 256>>>(decW, decb, out);
        if ((long long)out_size >= RE + ID)
            ids_out_kernel<<<(int)((ID + 255) / 256), 256>>>(out + RE, (int)ID);
    } else {
        ids_out_kernel<<<(out_size + 255) / 256, 256>>>(out, out_size);
    }
}

// round 10
// speedup vs baseline: 3.2935x; 1.4640x over previous
#include <cuda_runtime.h>
#include <cuda_bf16.h>
#include <cstdint>

#define NB   16384
#define DIN  1024
#define NL   4
#define NK   1024
#define CB   512

// ---------------------------------------------------------------------------
// Device scratch (no cudaMalloc allowed); 16B aligned for cp.async/float4.
// ---------------------------------------------------------------------------
__device__ __align__(16) float g_residf[NB * CB];   // fp32 residual (exact chain)
__device__ __align__(16) int   g_ids[NB * NL];
__device__ __align__(16) float g_cnorm[NL * NK];
__device__ __align__(16) __nv_bfloat16 g_Ahi[NB * CB];        // bf16 hi of residual
__device__ __align__(16) __nv_bfloat16 g_Chi[NL * NK * CB];   // bf16 hi of codebooks
// encoder operands: 2-way bf16 splits (3 pair-terms: 00, 01, 10)
__device__ __align__(16) __nv_bfloat16 g_X0[NB * DIN];
__device__ __align__(16) __nv_bfloat16 g_X1[NB * DIN];
__device__ __align__(16) __nv_bfloat16 g_W0[CB * DIN];        // enc_W^T splits [n][k]
__device__ __align__(16) __nv_bfloat16 g_W1[CB * DIN];

// ---------------------------------------------------------------------------
// helpers
// ---------------------------------------------------------------------------
__device__ __forceinline__ uint32_t smem_u32(const void* p) {
    uint32_t a;
    asm("{ .reg .u64 t; cvta.to.shared.u64 t, %1; cvt.u32.u64 %0, t; }"
        : "=r"(a) : "l"(p));
    return a;
}
__device__ __forceinline__ void cpa16(uint32_t s, const void* g) {
    asm volatile("cp.async.cg.shared.global [%0], [%1], 16;" :: "r"(s), "l"(g));
}
__device__ __forceinline__ uint32_t swz(uint32_t b) { return b ^ ((b >> 3) & 0x70); }

__device__ __forceinline__ void ldmA(uint32_t* a, uint32_t addr) {
    asm volatile("ldmatrix.sync.aligned.m8n8.x4.shared.b16 {%0,%1,%2,%3}, [%4];"
                 : "=r"(a[0]), "=r"(a[1]), "=r"(a[2]), "=r"(a[3]) : "r"(addr));
}
__device__ __forceinline__ void ldmB(uint32_t* b, uint32_t addr) {
    asm volatile("ldmatrix.sync.aligned.m8n8.x2.shared.b16 {%0,%1}, [%2];"
                 : "=r"(b[0]), "=r"(b[1]) : "r"(addr));
}
__device__ __forceinline__ void mma16816(float* c, const uint32_t* a, const uint32_t* b) {
    asm volatile(
        "mma.sync.aligned.m16n8k16.row.col.f32.bf16.bf16.f32 "
        "{%0,%1,%2,%3}, {%4,%5,%6,%7}, {%8,%9}, {%0,%1,%2,%3};"
        : "+f"(c[0]), "+f"(c[1]), "+f"(c[2]), "+f"(c[3])
        : "r"(a[0]), "r"(a[1]), "r"(a[2]), "r"(a[3]), "r"(b[0]), "r"(b[1]));
}

// ---------------------------------------------------------------------------
// Prep kernels
// ---------------------------------------------------------------------------
__global__ void cnorm_kernel(const float* __restrict__ codebooks) {
    int warp = (blockIdx.x * blockDim.x + threadIdx.x) >> 5;
    int lane = threadIdx.x & 31;
    if (warp >= NL * NK) return;
    const float* c = codebooks + (size_t)warp * CB;
    float s = 0.f;
    for (int t = lane; t < CB; t += 32) { float v = c[t]; s += v * v; }
    #pragma unroll
    for (int o = 16; o > 0; o >>= 1) s += __shfl_xor_sync(0xffffffffu, s, o);
    if (lane == 0) g_cnorm[warp] = s;
}

__global__ void xsplit_kernel(const float* __restrict__ X) {
    int i = blockIdx.x * blockDim.x + threadIdx.x;
    if (i >= NB * DIN) return;
    float v = X[i];
    __nv_bfloat16 s0 = __float2bfloat16(v);
    __nv_bfloat16 s1 = __float2bfloat16(v - __bfloat162float(s0));
    g_X0[i] = s0; g_X1[i] = s1;
}

__global__ void cbhi_kernel(const float* __restrict__ Cbs) {
    int i = blockIdx.x * blockDim.x + threadIdx.x;
    if (i >= NL * NK * CB) return;
    g_Chi[i] = __float2bfloat16(Cbs[i]);
}

__global__ void wsplitT_kernel(const float* __restrict__ W) {  // [DIN][CB] -> [CB][DIN]
    int i = blockIdx.x * blockDim.x + threadIdx.x;
    if (i >= CB * DIN) return;
    int n = i / DIN, k = i % DIN;
    float v = W[(size_t)k * CB + n];
    __nv_bfloat16 s0 = __float2bfloat16(v);
    __nv_bfloat16 s1 = __float2bfloat16(v - __bfloat162float(s0));
    g_W0[i] = s0; g_W1[i] = s1;
}

// ---------------------------------------------------------------------------
// Encoder: r0 = X @ W + b via 3-pair bf16 split on mma.sync (err ~1e-4 abs)
// CTA tile 128x128, 16 warps (4m x 4n), warp tile 32x32. 48 K-chunks of 64.
// ---------------------------------------------------------------------------
__global__ __launch_bounds__(512) void enc_mma_kernel(const float* __restrict__ encb) {
    extern __shared__ char dsm[];
    const uint32_t sb = smem_u32(dsm);
    const uint32_t Abuf[2] = { sb,          sb + 16384 };
    const uint32_t Bbuf[2] = { sb + 32768,  sb + 49152 };

    const int tid = threadIdx.x, wid = tid >> 5, lane = tid & 31;
    const int wm = wid >> 2, wn = wid & 3;
    const int g = lane >> 2, q = lane & 3;
    const int m0 = blockIdx.y * 128, n0 = blockIdx.x * 128;

    const __nv_bfloat16* TA[3] = { g_X0, g_X0, g_X1 };
    const __nv_bfloat16* TB[3] = { g_W0, g_W1, g_W0 };

    float acc[2][4][4];
    #pragma unroll
    for (int i = 0; i < 2; i++)
        #pragma unroll
        for (int j = 0; j < 4; j++)
            #pragma unroll
            for (int k = 0; k < 4; k++) acc[i][j][k] = 0.f;

    auto issue = [&](int p, int b) {
        int term = p >> 4, k0 = (p & 15) * 64;
        const __nv_bfloat16* As = TA[term];
        const __nv_bfloat16* Bs = TB[term];
        #pragma unroll
        for (int it = 0; it < 2; it++) {
            int w = tid + it * 512;
            int row = w >> 3, sg = w & 7;
            cpa16(Abuf[b] + swz((uint32_t)(row * 128 + sg * 16)),
                  As + (size_t)(m0 + row) * DIN + k0 + sg * 8);
        }
        #pragma unroll
        for (int it = 0; it < 2; it++) {
            int w = tid + it * 512;
            int row = w >> 3, sg = w & 7;
            cpa16(Bbuf[b] + swz((uint32_t)(row * 128 + sg * 16)),
                  Bs + (size_t)(n0 + row) * DIN + k0 + sg * 8);
        }
        asm volatile("cp.async.commit_group;");
    };

    issue(0, 0);

    #pragma unroll 1
    for (int p = 0; p < 48; p++) {
        if (p + 1 < 48) {
            issue(p + 1, (p + 1) & 1);
            asm volatile("cp.async.wait_group 1;" ::: "memory");
        } else {
            asm volatile("cp.async.wait_group 0;" ::: "memory");
        }
        __syncthreads();

        const uint32_t ab = Abuf[p & 1], bb = Bbuf[p & 1];
        #pragma unroll
        for (int kf = 0; kf < 4; kf++) {
            uint32_t af[2][4], bf[4][2];
            #pragma unroll
            for (int mf = 0; mf < 2; mf++) {
                int arow = wm * 32 + mf * 16 + (lane & 7) + ((lane >> 3) & 1) * 8;
                uint32_t koff = kf * 32 + (lane >> 4) * 16;
                ldmA(af[mf], ab + swz((uint32_t)(arow * 128) + koff));
            }
            #pragma unroll
            for (int nf = 0; nf < 4; nf++) {
                int l = lane & 15;
                int nrow = wn * 32 + nf * 8 + (l & 7);
                uint32_t koff = kf * 32 + ((l >> 3) & 1) * 16;
                ldmB(bf[nf], bb + swz((uint32_t)(nrow * 128) + koff));
            }
            #pragma unroll
            for (int mf = 0; mf < 2; mf++)
                #pragma unroll
                for (int nf = 0; nf < 4; nf++)
                    mma16816(acc[mf][nf], af[mf], bf[nf]);
        }
        __syncthreads();
    }

    // epilogue: bias + write fp32 residual and bf16 hi
    #pragma unroll
    for (int mf = 0; mf < 2; mf++) {
        #pragma unroll
        for (int nf = 0; nf < 4; nf++) {
            #pragma unroll
            for (int j = 0; j < 4; j++) {
                int row = m0 + wm * 32 + mf * 16 + g + (j >> 1) * 8;
                int col = n0 + wn * 32 + nf * 8 + q * 2 + (j & 1);
                float v = acc[mf][nf][j] + __ldg(&encb[col]);
                size_t o = (size_t)row * CB + col;
                g_residf[o] = v;
                g_Ahi[o]    = __float2bfloat16(v);
            }
        }
    }
}

// ---------------------------------------------------------------------------
// VQ layer: coarse bf16 scores (mma.sync) + top-3/owner + exact fp32 rescore
// within margin, then residual update + re-split hi.
// CTA: 128 rows x all 1024 codes, 16 warps (4m x 4n), warp tile 32x32.
// ---------------------------------------------------------------------------
__global__ __launch_bounds__(512) void vq_layer_kernel(const float* __restrict__ cbs,
                                                       int layer) {
    extern __shared__ char dsm[];
    const uint32_t sb    = smem_u32(dsm);
    const uint32_t A_off = sb;                 // 8 tiles x 16KB = 128KB
    const uint32_t B_off = sb + 131072;        // 2 bufs x 16KB
    float* red_d = (float*)dsm;                // [128][48] aliases A (used after loop)
    int*   red_i = (int*)(dsm + 128 * 48 * 4);
    __shared__ int bsel[128];

    const int tid = threadIdx.x, wid = tid >> 5, lane = tid & 31;
    const int wm = wid >> 2, wn = wid & 3;
    const int g = lane >> 2, q = lane & 3;
    const int m0 = blockIdx.x * 128;

    const __nv_bfloat16* Chi = g_Chi + (size_t)layer * NK * CB;
    const float* cn  = g_cnorm + layer * NK;
    const float* CbL = cbs + (size_t)layer * NK * CB;

    // load A (residual hi), 8 K-tiles of [128][64]
    #pragma unroll 1
    for (int it = 0; it < 16; it++) {
        int s = tid + it * 512;              // 0..8191 sectors
        int tile = s >> 10, w = s & 1023;
        int row = w >> 3, sg = w & 7;
        cpa16(A_off + tile * 16384 + swz((uint32_t)(row * 128 + sg * 16)),
              g_Ahi + (size_t)(m0 + row) * CB + tile * 64 + sg * 8);
    }
    asm volatile("cp.async.commit_group;");

    // prefetch B chunk 0 (nt=0, kc=0)
    #pragma unroll
    for (int it = 0; it < 2; it++) {
        int w = tid + it * 512;
        int row = w >> 3, sg = w & 7;
        cpa16(B_off + swz((uint32_t)(row * 128 + sg * 16)),
              Chi + (size_t)row * CB + sg * 8);
    }
    asm volatile("cp.async.commit_group;");

    float t3d[4][3]; int t3i[4][3];
    #pragma unroll
    for (int r = 0; r < 4; r++) {
        t3d[r][0] = t3d[r][1] = t3d[r][2] = 3.4e38f;
        t3i[r][0] = t3i[r][1] = t3i[r][2] = 0;
    }

    float acc[2][4][4];

    #pragma unroll 1
    for (int p = 0; p < 64; p++) {
        const int nt = p >> 3, kc = p & 7;
        if (p + 1 < 64) {
            const int nnt = (p + 1) >> 3, nkc = (p + 1) & 7;
            uint32_t bb = B_off + ((p + 1) & 1) * 16384;
            #pragma unroll
            for (int it = 0; it < 2; it++) {
                int w = tid + it * 512;
                int row = w >> 3, sg = w & 7;
                cpa16(bb + swz((uint32_t)(row * 128 + sg * 16)),
                      Chi + (size_t)(nnt * 128 + row) * CB + nkc * 64 + sg * 8);
            }
            asm volatile("cp.async.commit_group;");
            asm volatile("cp.async.wait_group 1;" ::: "memory");
        } else {
            asm volatile("cp.async.wait_group 0;" ::: "memory");
        }
        __syncthreads();

        if (kc == 0) {
            #pragma unroll
            for (int i = 0; i < 2; i++)
                #pragma unroll
                for (int j = 0; j < 4; j++)
                    #pragma unroll
                    for (int k = 0; k < 4; k++) acc[i][j][k] = 0.f;
        }

        const uint32_t ab = A_off + kc * 16384;
        const uint32_t bb = B_off + (p & 1) * 16384;
        #pragma unroll
        for (int kf = 0; kf < 4; kf++) {
            uint32_t af[2][4], bf[4][2];
            #pragma unroll
            for (int mf = 0; mf < 2; mf++) {
                int arow = wm * 32 + mf * 16 + (lane & 7) + ((lane >> 3) & 1) * 8;
                uint32_t koff = kf * 32 + (lane >> 4) * 16;
                ldmA(af[mf], ab + swz((uint32_t)(arow * 128) + koff));
            }
            #pragma unroll
            for (int nf = 0; nf < 4; nf++) {
                int l = lane & 15;
                int nrow = wn * 32 + nf * 8 + (l & 7);
                uint32_t koff = kf * 32 + ((l >> 3) & 1) * 16;
                ldmB(bf[nf], bb + swz((uint32_t)(nrow * 128) + koff));
            }
            #pragma unroll
            for (int mf = 0; mf < 2; mf++)
                #pragma unroll
                for (int nf = 0; nf < 4; nf++)
                    mma16816(acc[mf][nf], af[mf], bf[nf]);
        }

        if (kc == 7) {   // fold this code tile into per-thread top-3
            #pragma unroll
            for (int mf = 0; mf < 2; mf++) {
                #pragma unroll
                for (int nf = 0; nf < 4; nf++) {
                    int colbase = nt * 128 + wn * 32 + nf * 8 + q * 2;
                    #pragma unroll
                    for (int j = 0; j < 4; j++) {
                        int code = colbase + (j & 1);
                        float d = __ldg(&cn[code]) - 2.f * acc[mf][nf][j];
                        int rs = mf * 2 + (j >> 1);
                        if (d < t3d[rs][2]) {
                            if (d < t3d[rs][1]) {
                                t3d[rs][2] = t3d[rs][1]; t3i[rs][2] = t3i[rs][1];
                                if (d < t3d[rs][0]) {
                                    t3d[rs][1] = t3d[rs][0]; t3i[rs][1] = t3i[rs][0];
                                    t3d[rs][0] = d; t3i[rs][0] = code;
                                } else { t3d[rs][1] = d; t3i[rs][1] = code; }
                            } else { t3d[rs][2] = d; t3i[rs][2] = code; }
                        }
                    }
                }
            }
        }
        __syncthreads();
    }

    // dump per-owner top-3 (A smem region is free now)
    #pragma unroll
    for (int rs = 0; rs < 4; rs++) {
        int mf = rs >> 1, h = rs & 1;
        int row = wm * 32 + mf * 16 + g + h * 8;
        int owner = wn * 4 + q;               // 0..15
        #pragma unroll
        for (int j = 0; j < 3; j++) {
            red_d[row * 48 + owner * 3 + j] = t3d[rs][j];
            red_i[row * 48 + owner * 3 + j] = t3i[rs][j];
        }
    }
    __syncthreads();

    // exact fp32 rescore within margin of coarse min: 4 threads per row
    {
        int row = tid >> 2, sub = tid & 3;    // 512 threads -> 128 rows x 4
        const float* rd = red_d + row * 48;
        const int*   ri = red_i + row * 48;
        float lmin = 3.4e38f;
        #pragma unroll 1
        for (int e = sub * 12; e < sub * 12 + 12; e++) lmin = fminf(lmin, rd[e]);
        #pragma unroll
        for (int o = 1; o < 4; o <<= 1) lmin = fminf(lmin, __shfl_xor_sync(0xffffffffu, lmin, o));
        const float TAU = 1.5f;
        float bd = 3.4e38f; int bi = 0x7fffffff;
        const float* R = g_residf + (size_t)(m0 + row) * CB;
        #pragma unroll 1
        for (int e = sub * 12; e < sub * 12 + 12; e++) {
            if (rd[e] <= lmin + TAU) {
                int c = ri[e];
                const float* C = CbL + (size_t)c * CB;
                float s0 = 0.f, s1 = 0.f, s2 = 0.f, s3 = 0.f;
                #pragma unroll 4
                for (int k = 0; k < CB; k += 4) {
                    s0 += R[k]     * C[k];
                    s1 += R[k + 1] * C[k + 1];
                    s2 += R[k + 2] * C[k + 2];
                    s3 += R[k + 3] * C[k + 3];
                }
                float de = __ldg(&cn[c]) - 2.f * ((s0 + s1) + (s2 + s3));
                if (de < bd || (de == bd && c < bi)) { bd = de; bi = c; }
            }
        }
        #pragma unroll
        for (int o = 1; o < 4; o <<= 1) {
            float od = __shfl_xor_sync(0xffffffffu, bd, o);
            int   oi = __shfl_xor_sync(0xffffffffu, bi, o);
            if (od < bd || (od == bd && oi < bi)) { bd = od; bi = oi; }
        }
        if (sub == 0) {
            bsel[row] = bi;
            g_ids[(size_t)(m0 + row) * NL + layer] = bi;
        }
    }
    __syncthreads();

    // residual -= codebook[best]; store fp32 + bf16 hi for next layer
    #pragma unroll 1
    for (int e = tid; e < 128 * (CB / 4); e += 512) {
        int r = e >> 7, c4 = (e & 127) * 4;
        int ci = bsel[r];
        size_t ro = (size_t)(m0 + r) * CB + c4;
        float4 rv = *(float4*)&g_residf[ro];
        float4 cv = *(const float4*)&CbL[(size_t)ci * CB + c4];
        rv.x -= cv.x; rv.y -= cv.y; rv.z -= cv.z; rv.w -= cv.w;
        *(float4*)&g_residf[ro] = rv;
        if (layer < NL - 1) {
            __nv_bfloat162 h0{__float2bfloat16(rv.x), __float2bfloat16(rv.y)};
            __nv_bfloat162 h1{__float2bfloat16(rv.z), __float2bfloat16(rv.w)};
            *(__nv_bfloat162*)&g_Ahi[ro]     = h0;
            *(__nv_bfloat162*)&g_Ahi[ro + 2] = h1;
        }
    }
}

// ---------------------------------------------------------------------------
// Decoder + ids output (exact, unchanged from passing baseline)
// ---------------------------------------------------------------------------
__global__ void decode_kernel(const float* __restrict__ dec_W,
                              const float* __restrict__ dec_b,
                              float* __restrict__ out) {
    int idx = blockIdx.x * blockDim.x + threadIdx.x;
    if (idx >= NB * CB) return;
    int b = idx / CB, j = idx % CB;
    const int* ids = &g_ids[b * NL];
    float s = dec_b[j];
    #pragma unroll
    for (int l = 0; l < NL; l++)
        s += (float)ids[l] * dec_W[l * CB + j];
    out[idx] = s;
}

__global__ void ids_out_kernel(float* __restrict__ out, int n) {
    int idx = blockIdx.x * blockDim.x + threadIdx.x;
    if (idx < n) out[idx] = (float)g_ids[idx];
}

// ---------------------------------------------------------------------------
extern "C" void kernel_launch(void* const* d_in, const int* in_sizes, int n_in,
                              void* d_out, int out_size) {
    (void)in_sizes; (void)n_in;
    const float* X    = (const float*)d_in[0];
    const float* encW = (const float*)d_in[1];
    const float* encb = (const float*)d_in[2];
    const float* cbs  = (const float*)d_in[3];
    const float* decW = (const float*)d_in[4];
    const float* decb = (const float*)d_in[5];
    float* out = (float*)d_out;

    const int VQ_SMEM  = 131072 + 2 * 16384;   // 163840
    const int ENC_SMEM = 4 * 16384;            // 65536
    cudaFuncSetAttribute(vq_layer_kernel, cudaFuncAttributeMaxDynamicSharedMemorySize, VQ_SMEM);
    cudaFuncSetAttribute(enc_mma_kernel,  cudaFuncAttributeMaxDynamicSharedMemorySize, ENC_SMEM);

    // prep
    cnorm_kernel<<<(NL * NK * 32 + 255) / 256, 256>>>(cbs);
    xsplit_kernel<<<(NB * DIN + 255) / 256, 256>>>(X);
    cbhi_kernel<<<(NL * NK * CB + 255) / 256, 256>>>(cbs);
    wsplitT_kernel<<<(CB * DIN + 255) / 256, 256>>>(encW);

    // encoder (tensor cores, 3-pair split)
    dim3 gEnc(CB / 128, NB / 128);
    enc_mma_kernel<<<gEnc, 512, ENC_SMEM>>>(encb);

    // VQ layers (tensor-core coarse + exact rescore)
    for (int l = 0; l < NL; l++)
        vq_layer_kernel<<<NB / 128, 512, VQ_SMEM>>>(cbs, l);

    const long long RE = (long long)NB * CB;   // 8388608
    const long long ID = (long long)NB * NL;   // 65536

    if ((long long)out_size >= RE) {
        decode_kernel<<<(NB * CB + 255) / 256, 256>>>(decW, decb, out);
        if ((long long)out_size >= RE + ID)
            ids_out_kernel<<<(int)((ID + 255) / 256), 256>>>(out + RE, (int)ID);
    } else {
        ids_out_kernel<<<(out_size + 255) / 256, 256>>>(out, out_size);
    }
}